// round 1
// baseline (speedup 1.0000x reference)
#include <cuda_runtime.h>

#define HH 96
#define WW 96
#define HW 9216
#define NE 64
#define ND 128
#define NK 4
#define NB 2

// -------- scratch (no allocations allowed) --------
__device__ float g_queries[NB * NE * HW];
__device__ float g_keys[NK * NB * NE * HW];
__device__ float g_values[NB * NE * HW];

__device__ __forceinline__ float fast_tanh(float x) {
    // tanh(x) = 1 - 2/(e^{2x}+1); safe at +/-inf, ~1e-6 rel err
    float e = __expf(2.0f * x);
    return 1.0f - __fdividef(2.0f, e + 1.0f);
}

// ============================================================
// 1x1 conv:  out[img][o][p] = sum_ci w[o][ci] * x[img][ci][p] + b[o]
// block: 64 out channels x 128 pixels. 256 threads, 8ch x 4px per thread.
// ============================================================
template <int CIN>
__global__ void __launch_bounds__(256) conv1x1_kernel(
    const float* __restrict__ x, const float* __restrict__ w,
    const float* __restrict__ bias, float* __restrict__ out)
{
    __shared__ __align__(16) float xs[16][128];
    __shared__ __align__(16) float ws[16][64];
    int tid = threadIdx.x;
    int lane = tid & 31, cg = tid >> 5;
    int img = blockIdx.y;
    int p0 = blockIdx.x * 128;
    const float* xb = x + (size_t)img * CIN * HW + p0;

    float acc[8][4];
#pragma unroll
    for (int e = 0; e < 8; e++)
#pragma unroll
        for (int j = 0; j < 4; j++) acc[e][j] = 0.f;

    for (int c0 = 0; c0 < CIN; c0 += 16) {
#pragma unroll
        for (int rep = 0; rep < 2; rep++) {
            int lin = tid + rep * 256;
            int ci = lin >> 5, px = (lin & 31) * 4;
            *(float4*)&xs[ci][px] = *(const float4*)&xb[(size_t)(c0 + ci) * HW + px];
        }
        {
            int ci = tid >> 4, o4 = (tid & 15) * 4;
#pragma unroll
            for (int t = 0; t < 4; t++)
                ws[ci][o4 + t] = w[(o4 + t) * CIN + c0 + ci];
        }
        __syncthreads();
#pragma unroll
        for (int ci = 0; ci < 16; ci++) {
            float4 xv = *(float4*)&xs[ci][lane * 4];
            float4 wa = *(float4*)&ws[ci][cg * 8];
            float4 wb = *(float4*)&ws[ci][cg * 8 + 4];
            float xvv[4] = {xv.x, xv.y, xv.z, xv.w};
            float wv[8] = {wa.x, wa.y, wa.z, wa.w, wb.x, wb.y, wb.z, wb.w};
#pragma unroll
            for (int e = 0; e < 8; e++)
#pragma unroll
                for (int j = 0; j < 4; j++)
                    acc[e][j] = fmaf(wv[e], xvv[j], acc[e][j]);
        }
        __syncthreads();
    }
    float* ob = out + (size_t)img * NE * HW + p0;
#pragma unroll
    for (int e = 0; e < 8; e++) {
        int o = cg * 8 + e;
        float bb = bias[o];
        float4 r = make_float4(acc[e][0] + bb, acc[e][1] + bb,
                               acc[e][2] + bb, acc[e][3] + bb);
        *(float4*)&ob[(size_t)o * HW + lane * 4] = r;
    }
}

// ============================================================
// 3x3 conv (SAME, cross-correlation): 128 -> 64 channels.
// 8x8 pixel tiles, grid (12,12,B) = 288 blocks. 256 threads:
// cg=tid>>5 -> 8 channels; lane -> (prow=lane>>2, pcol0=(lane&3)*2) -> 2 px.
// ============================================================
__global__ void __launch_bounds__(256) conv3x3_kernel(
    const float* __restrict__ x,    // [B][128][H][W]
    const float* __restrict__ wv,   // [64][128][3][3]
    const float* __restrict__ bias, // [64]
    float* __restrict__ out)        // [B][64][H][W]
{
    __shared__ __align__(16) float xs[16][110];     // [ci][hr*11+hc], 10x10 halo
    __shared__ __align__(16) float ws[16][9][64];   // repacked [ci][tap][o]
    int tid = threadIdx.x;
    int lane = tid & 31, cg = tid >> 5;
    int b = blockIdx.z;
    int yo = blockIdx.y * 8, xo = blockIdx.x * 8;
    int prow = lane >> 2, pcol0 = (lane & 3) * 2;
    const float* xb = x + (size_t)b * ND * HW;

    float acc[8][2];
#pragma unroll
    for (int e = 0; e < 8; e++) { acc[e][0] = 0.f; acc[e][1] = 0.f; }

    for (int c0 = 0; c0 < ND; c0 += 16) {
        for (int lin = tid; lin < 1600; lin += 256) {
            int hc = lin % 10; int t = lin / 10; int hr = t % 10; int ci = t / 10;
            int gy = yo - 1 + hr, gx = xo - 1 + hc;
            float v = 0.f;
            if ((unsigned)gy < HH && (unsigned)gx < WW)
                v = xb[(size_t)(c0 + ci) * HW + gy * WW + gx];
            xs[ci][hr * 11 + hc] = v;
        }
        for (int lin = tid; lin < 9216; lin += 256) {
            int o = lin & 63; int t = lin >> 6; int tap = t % 9; int ci = t / 9;
            ws[ci][tap][o] = wv[(size_t)o * (ND * 9) + (c0 + ci) * 9 + tap];
        }
        __syncthreads();
#pragma unroll
        for (int ci = 0; ci < 16; ci++) {
#pragma unroll
            for (int dr = 0; dr < 3; dr++) {
                float xr[4];
#pragma unroll
                for (int i = 0; i < 4; i++)
                    xr[i] = xs[ci][(prow + dr) * 11 + pcol0 + i];
#pragma unroll
                for (int dc = 0; dc < 3; dc++) {
                    float4 wa = *(float4*)&ws[ci][dr * 3 + dc][cg * 8];
                    float4 wb = *(float4*)&ws[ci][dr * 3 + dc][cg * 8 + 4];
                    float wr[8] = {wa.x, wa.y, wa.z, wa.w, wb.x, wb.y, wb.z, wb.w};
#pragma unroll
                    for (int e = 0; e < 8; e++) {
                        acc[e][0] = fmaf(wr[e], xr[dc], acc[e][0]);
                        acc[e][1] = fmaf(wr[e], xr[dc + 1], acc[e][1]);
                    }
                }
            }
        }
        __syncthreads();
    }
    float* ob = out + (size_t)b * NE * HW;
#pragma unroll
    for (int e = 0; e < 8; e++) {
        int o = cg * 8 + e;
        float bb = bias[o];
        float2 r = make_float2(acc[e][0] + bb, acc[e][1] + bb);
        *(float2*)&ob[(size_t)o * HW + (yo + prow) * WW + xo + pcol0] = r;
    }
}

// ============================================================
// Fused attention + output projection.
// 8x8 pixel tile per block, 8 warps, warp = tile row; lanes over E.
// ============================================================
__device__ __forceinline__ void final_accum(
    const float* __restrict__ cat, const float* __restrict__ wsl,
    int lane, int wr, float out0[8], float out1[8])
{
#pragma unroll
    for (int it = 0; it < 8; it++) {
        int i0 = it * 8;
        float w0[8], w1[8];
#pragma unroll
        for (int jj = 0; jj < 8; jj++) {
            w0[jj] = wsl[(i0 + jj) * 65 + lane];
            w1[jj] = wsl[(i0 + jj) * 65 + 32 + lane];
        }
#pragma unroll
        for (int j = 0; j < 8; j++) {
            const float* cp = &cat[(wr * 8 + j) * 68 + i0];
            float4 ca = *(const float4*)cp;
            float4 cb = *(const float4*)(cp + 4);
            float s0 = out0[j];
            s0 = fmaf(w0[0], ca.x, s0); s0 = fmaf(w0[1], ca.y, s0);
            s0 = fmaf(w0[2], ca.z, s0); s0 = fmaf(w0[3], ca.w, s0);
            s0 = fmaf(w0[4], cb.x, s0); s0 = fmaf(w0[5], cb.y, s0);
            s0 = fmaf(w0[6], cb.z, s0); s0 = fmaf(w0[7], cb.w, s0);
            out0[j] = s0;
            float s1 = out1[j];
            s1 = fmaf(w1[0], ca.x, s1); s1 = fmaf(w1[1], ca.y, s1);
            s1 = fmaf(w1[2], ca.z, s1); s1 = fmaf(w1[3], ca.w, s1);
            s1 = fmaf(w1[4], cb.x, s1); s1 = fmaf(w1[5], cb.y, s1);
            s1 = fmaf(w1[6], cb.z, s1); s1 = fmaf(w1[7], cb.w, s1);
            out1[j] = s1;
        }
    }
}

__global__ void __launch_bounds__(256) attn_kernel(
    const float* __restrict__ contexts,  // [K][B][E][H][W]
    const float* __restrict__ w_agg,     // [64]
    const float* __restrict__ b_agg_p,   // [1]
    const float* __restrict__ w_attn,    // [64][320]
    const float* __restrict__ b_attn,    // [64]
    float* __restrict__ out)             // [B][64][H][W]
{
    extern __shared__ __align__(16) float sm[];
    float* qs  = sm;                  // [64 pix][68]
    float* ks  = qs + 64 * 68;        // [100 halo pix][68]
    float* cs  = ks + 100 * 68;       // [100 halo pix][68]
    float* cat = cs + 100 * 68;       // [64 pix][68]
    float* wsl = cat + 64 * 68;       // [64 i][65] (w_attn slice, [i][o])

    int tid = threadIdx.x, lane = tid & 31, wr = tid >> 5;
    int b = blockIdx.z, yo = blockIdx.y * 8, xo = blockIdx.x * 8;

    float wagg0 = w_agg[lane], wagg1 = w_agg[lane + 32];
    float bagg = b_agg_p[0];

    // load queries tile + values tile (-> cat) + w_attn slice 0
    for (int lin = tid; lin < 4096; lin += 256) {
        int col = lin & 7, row = (lin >> 3) & 7, e = lin >> 6;
        int g = (b * NE + e) * HW + (yo + row) * WW + xo + col;
        qs[(row * 8 + col) * 68 + e] = g_queries[g];
        cat[(row * 8 + col) * 68 + e] = g_values[g];
    }
    for (int lin = tid; lin < 4096; lin += 256) {
        int i = lin & 63, o = lin >> 6;
        wsl[i * 65 + o] = w_attn[o * 320 + i];
    }
    __syncthreads();

    float out0[8], out1[8];
#pragma unroll
    for (int j = 0; j < 8; j++) { out0[j] = 0.f; out1[j] = 0.f; }
    final_accum(cat, wsl, lane, wr, out0, out1);

    for (int k = 0; k < NK; k++) {
        __syncthreads();
        const float* kb = g_keys + (size_t)(k * NB + b) * NE * HW;
        const float* cb = contexts + (size_t)(k * NB + b) * NE * HW;
        for (int lin = tid; lin < 6400; lin += 256) {
            int hc = lin % 10; int t = lin / 10; int hr = t % 10; int e = t / 10;
            int gy = yo - 1 + hr, gx = xo - 1 + hc;
            float kv = 0.f, cv = 0.f;
            if ((unsigned)gy < HH && (unsigned)gx < WW) {
                int g = e * HW + gy * WW + gx;
                kv = kb[g]; cv = cb[g];
            }
            ks[(hr * 10 + hc) * 68 + e] = kv;
            cs[(hr * 10 + hc) * 68 + e] = cv;
        }
        for (int lin = tid; lin < 4096; lin += 256) {
            int i = lin & 63, o = lin >> 6;
            wsl[i * 65 + o] = w_attn[o * 320 + (k + 1) * 64 + i];
        }
        __syncthreads();

        for (int j = 0; j < 8; j++) {
            int pix = wr * 8 + j;
            float q0 = qs[pix * 68 + lane];
            float q1 = qs[pix * 68 + 32 + lane];
            float sc[9];
#pragma unroll
            for (int n = 0; n < 9; n++) {
                int dr = n / 3, dc = n % 3;
                int hp = (wr + dr) * 10 + (j + dc);
                float t0 = fast_tanh(q0 + ks[hp * 68 + lane]);
                float t1 = fast_tanh(q1 + ks[hp * 68 + 32 + lane]);
                float part = fmaf(wagg0, t0, wagg1 * t1);
#pragma unroll
                for (int off = 16; off; off >>= 1)
                    part += __shfl_xor_sync(0xffffffffu, part, off);
                bool valid = ((unsigned)(yo + wr + dr - 1) < HH) &&
                             ((unsigned)(xo + j + dc - 1) < WW);
                sc[n] = valid ? (part + bagg) : -1e30f;
            }
            float m = sc[0];
#pragma unroll
            for (int n = 1; n < 9; n++) m = fmaxf(m, sc[n]);
            float p[9], ps = 0.f;
#pragma unroll
            for (int n = 0; n < 9; n++) { p[n] = __expf(sc[n] - m); ps += p[n]; }
            float rinv = 1.0f / ps;
            float a0 = 0.f, a1 = 0.f;
#pragma unroll
            for (int n = 0; n < 9; n++) {
                int hp = (wr + n / 3) * 10 + (j + n % 3);
                a0 = fmaf(p[n], cs[hp * 68 + lane], a0);
                a1 = fmaf(p[n], cs[hp * 68 + 32 + lane], a1);
            }
            cat[pix * 68 + lane] = a0 * rinv;
            cat[pix * 68 + 32 + lane] = a1 * rinv;
        }
        __syncwarp();
        final_accum(cat, wsl, lane, wr, out0, out1);
    }

    // epilogue: bias + LeakyReLU(0.2), transpose through smem, coalesced store
    float ba0 = b_attn[lane], ba1 = b_attn[lane + 32];
    __syncthreads();
#pragma unroll
    for (int j = 0; j < 8; j++) {
        int pix = wr * 8 + j;
        float r0 = out0[j] + ba0; r0 = (r0 >= 0.f) ? r0 : 0.2f * r0;
        float r1 = out1[j] + ba1; r1 = (r1 >= 0.f) ? r1 : 0.2f * r1;
        cat[pix * 68 + lane] = r0;
        cat[pix * 68 + 32 + lane] = r1;
    }
    __syncthreads();
    for (int lin = tid; lin < 4096; lin += 256) {
        int col = lin & 7, row = (lin >> 3) & 7, e = lin >> 6;
        out[(b * NE + e) * HW + (yo + row) * WW + xo + col] =
            cat[(row * 8 + col) * 68 + e];
    }
}

// ============================================================
extern "C" void kernel_launch(void* const* d_in, const int* in_sizes, int n_in,
                              void* d_out, int out_size)
{
    (void)in_sizes; (void)n_in; (void)out_size;
    const float* contexts = (const float*)d_in[0];
    const float* decoded  = (const float*)d_in[1];
    const float* w_enc    = (const float*)d_in[2];
    const float* b_enc    = (const float*)d_in[3];
    const float* w_dec    = (const float*)d_in[4];
    const float* b_dec    = (const float*)d_in[5];
    const float* w_agg    = (const float*)d_in[6];
    const float* b_agg    = (const float*)d_in[7];
    const float* w_val    = (const float*)d_in[8];
    const float* b_val    = (const float*)d_in[9];
    const float* w_attn   = (const float*)d_in[10];
    const float* b_attn   = (const float*)d_in[11];
    float* out = (float*)d_out;

    float *gq, *gk, *gv;
    cudaGetSymbolAddress((void**)&gq, g_queries);
    cudaGetSymbolAddress((void**)&gk, g_keys);
    cudaGetSymbolAddress((void**)&gv, g_values);

    conv1x1_kernel<ND><<<dim3(72, NB), 256>>>(decoded, w_dec, b_dec, gq);
    conv1x1_kernel<NE><<<dim3(72, NK * NB), 256>>>(contexts, w_enc, b_enc, gk);
    conv3x3_kernel<<<dim3(12, 12, NB), 256>>>(decoded, w_val, b_val, gv);

    const int SMEM_ATTN = (64 * 68 + 100 * 68 + 100 * 68 + 64 * 68 + 64 * 65) * 4;
    cudaFuncSetAttribute(attn_kernel,
                         cudaFuncAttributeMaxDynamicSharedMemorySize, SMEM_ATTN);
    attn_kernel<<<dim3(12, 12, NB), 256, SMEM_ATTN>>>(
        contexts, w_agg, b_agg, w_attn, b_attn, out);
}